// round 3
// baseline (speedup 1.0000x reference)
#include <cuda_runtime.h>

#define N 8192
#define NBOX 16
#define MIN_SCORE 0.3f
#define NMS_THR 0.3f
#define MAX_OUT 256

// scratch (no allocations allowed)
__device__ int g_order[N];
__device__ float g_ssort[N];
__device__ unsigned g_partial[2][N];

// ---------------------------------------------------------------------------
// Rank sort, stage 1: partial ranks over half the j-range per block.
// rank(i) = #{j<i : s_j >= s_i} + #{j>=i : s_j > s_i}
// (exactly matches stable argsort(-s): ties broken by ascending index)
// grid (64, 2) x 128 threads -> 128 blocks, each j-half tiled in smem.
// ---------------------------------------------------------------------------
__global__ __launch_bounds__(128) void rank_partial_kernel(const float* __restrict__ score)
{
    __shared__ float sh[4096];
    const int jlo = blockIdx.y * 4096;
    for (int r = threadIdx.x; r < 4096; r += 128) sh[r] = score[jlo + r];
    __syncthreads();

    const int i = blockIdx.x * 128 + threadIdx.x;
    const float si = score[i];

    int m = i - jlo;                    // local boundary: local j < m  <=>  global j < i
    m = m < 0 ? 0 : (m > 4096 ? 4096 : m);

    int cnt = 0;
    const float4* sh4 = reinterpret_cast<const float4*>(sh);

    const int m4 = m >> 2;
    for (int q = 0; q < m4; ++q) {
        float4 v = sh4[q];
        cnt += (v.x >= si) + (v.y >= si) + (v.z >= si) + (v.w >= si);
    }
    for (int r = m4 << 2; r < m; ++r) cnt += (sh[r] >= si);

    const int q0 = (m + 3) >> 2;
    int rend = q0 << 2; if (rend > 4096) rend = 4096;
    for (int r = m; r < rend; ++r) cnt += (sh[r] > si);
    for (int q = q0; q < 1024; ++q) {
        float4 v = sh4[q];
        cnt += (v.x > si) + (v.y > si) + (v.z > si) + (v.w > si);
    }

    g_partial[blockIdx.y][i] = (unsigned)cnt;
}

// Stage 2: combine partials, scatter index + score into sorted position.
__global__ __launch_bounds__(256) void rank_scatter_kernel(const float* __restrict__ score)
{
    const int i = blockIdx.x * 256 + threadIdx.x;
    const unsigned rank = g_partial[0][i] + g_partial[1][i];
    g_order[rank] = i;
    g_ssort[rank] = score[i];
}

// ---------------------------------------------------------------------------
// Greedy NMS + output. Single block, 1024 threads, 8 boxes/thread in regs.
// Each round: suppress vs. last-kept box (broadcast in smem), then two
// hardware min-reductions find the smallest still-alive index = next kept.
// All floating point mirrors the reference op-for-op (no FMA contraction,
// IEEE division) so the iou > 0.3 decisions match bit-for-bit.
// ---------------------------------------------------------------------------
__global__ __launch_bounds__(1024, 1) void nms_kernel(const float* __restrict__ box,
                                                      float* __restrict__ out)
{
    __shared__ float s_bx1, s_by1, s_bx2, s_by2, s_barea;
    __shared__ int s_warpmin[32];
    __shared__ int s_kept[MAX_OUT];

    const int t = threadIdx.x;
    const int lane = t & 31, wid = t >> 5;

    float x1[8], y1[8], x2[8], y2[8], ar[8];
    unsigned alive = 0;

#pragma unroll
    for (int k = 0; k < 8; ++k) {
        const int i = t + (k << 10);
        const float s = g_ssort[i];
        const int orig = g_order[i];
        const float4 b = *reinterpret_cast<const float4*>(box + (size_t)orig * NBOX);
        const float hw = __fmul_rn(b.z, 0.5f);
        const float hh = __fmul_rn(b.w, 0.5f);
        x1[k] = __fsub_rn(b.x, hw);
        y1[k] = __fsub_rn(b.y, hh);
        x2[k] = __fadd_rn(b.x, hw);
        y2[k] = __fadd_rn(b.y, hh);
        ar[k] = __fmul_rn(__fsub_rn(x2[k], x1[k]), __fsub_rn(y2[k], y1[k]));
        if (s >= MIN_SCORE) alive |= (1u << k);
    }

    if (t == 0) {
        // degenerate "kept box": intersects nothing, iou = 0 for all
        s_bx1 = 3e30f; s_by1 = 3e30f; s_bx2 = -3e30f; s_by2 = -3e30f; s_barea = 0.0f;
    }
    __syncthreads();

    int nk = 0;  // kept count, uniform across threads (nb is uniform each round)
    while (true) {
        const float bx1 = s_bx1, by1 = s_by1, bx2 = s_bx2, by2 = s_by2, barea = s_barea;
        unsigned localmin = 0xffffffffu;
#pragma unroll
        for (int k = 0; k < 8; ++k) {
            if (alive & (1u << k)) {
                const float ltx = fmaxf(x1[k], bx1);
                const float lty = fmaxf(y1[k], by1);
                const float rbx = fminf(x2[k], bx2);
                const float rby = fminf(y2[k], by2);
                const float w = fmaxf(__fsub_rn(rbx, ltx), 0.0f);
                const float h = fmaxf(__fsub_rn(rby, lty), 0.0f);
                const float inter = __fmul_rn(w, h);
                const float denom =
                    __fadd_rn(__fsub_rn(__fadd_rn(barea, ar[k]), inter), 1e-9f);
                const float iou = __fdiv_rn(inter, denom);
                if (iou > NMS_THR) {
                    alive &= ~(1u << k);
                } else {
                    const unsigned idx = (unsigned)(t + (k << 10));
                    localmin = localmin < idx ? localmin : idx;
                }
            }
        }

        const unsigned wmin = __reduce_min_sync(0xffffffffu, localmin);
        if (lane == 0) s_warpmin[wid] = (int)wmin;
        __syncthreads();
        const unsigned nb = __reduce_min_sync(0xffffffffu, (unsigned)s_warpmin[lane]);

        if (nb == 0xffffffffu || nk >= MAX_OUT) break;

        if (t == (int)(nb & 1023u)) {
            const int k = (int)(nb >> 10);
            alive &= ~(1u << k);
            s_bx1 = x1[k]; s_by1 = y1[k]; s_bx2 = x2[k]; s_by2 = y2[k];
            s_barea = ar[k];
        }
        if (t == 0) s_kept[nk] = (int)nb;
        ++nk;
        __syncthreads();
    }
    __syncthreads();

    // Output: [score(256) | box(256x16) | valid(256)] as float32.
    // 4 threads per slot, each writes a float4 of the 16 box coords.
    const int slot = t >> 2, part = t & 3;
    float4 vb = make_float4(0.0f, 0.0f, 0.0f, 0.0f);
    float sc = 0.0f, vl = 0.0f;
    if (slot < nk) {
        const int si = s_kept[slot];
        const int orig = g_order[si];
        vb = *reinterpret_cast<const float4*>(box + (size_t)orig * NBOX + part * 4);
        sc = g_ssort[si];
        vl = 1.0f;
    }
    *reinterpret_cast<float4*>(out + 256 + slot * 16 + part * 4) = vb;
    if (part == 0) {
        out[slot] = sc;
        out[4352 + slot] = vl;
    }
}

extern "C" void kernel_launch(void* const* d_in, const int* in_sizes, int n_in,
                              void* d_out, int out_size)
{
    (void)in_sizes; (void)n_in; (void)out_size;
    const float* score = (const float*)d_in[0];
    const float* box   = (const float*)d_in[1];
    float* out = (float*)d_out;

    rank_partial_kernel<<<dim3(64, 2), 128>>>(score);
    rank_scatter_kernel<<<32, 256>>>(score);
    nms_kernel<<<1, 1024>>>(box, out);
}

// round 4
// speedup vs baseline: 2.5540x; 2.5540x over previous
#include <cuda_runtime.h>

#define N 8192
#define NW 256            // 32-bit words per mask row (8192/32)
#define MIN_SCORE 0.3f
#define NMS_THR 0.3f
#define MAX_OUT 256

// scratch (no allocations allowed; zero-initialized at module load)
__device__ int      g_order[N];
__device__ float    g_ssort[N];
__device__ unsigned g_partial[8][N];
__device__ float4   g_sxyxy[N];       // sorted-order xyxy
__device__ float    g_sarea[N];       // sorted-order area
__device__ unsigned g_valid[NW];      // score >= MIN_SCORE, by sorted rank
__device__ unsigned g_mask[N][NW];    // suppression matrix, 8MB (L2-resident)

// ---------------------------------------------------------------------------
// Rank sort, stage 1: partial ranks over a 1024-wide j-tile per block.
// rank(i) = #{j<i : s_j >= s_i} + #{j>=i : s_j > s_i}
// (exactly matches stable argsort(-s): ties broken by ascending index)
// grid (64, 8) x 128 threads.  Block (0,0) also re-zeroes g_valid each launch.
// ---------------------------------------------------------------------------
__global__ __launch_bounds__(128) void rank_partial_kernel(const float* __restrict__ score)
{
    __shared__ float sh[1024];
    const int jlo = blockIdx.y << 10;
    for (int r = threadIdx.x; r < 1024; r += 128) sh[r] = score[jlo + r];
    if (blockIdx.x == 0 && blockIdx.y == 0) {
        g_valid[threadIdx.x] = 0;
        g_valid[threadIdx.x + 128] = 0;
    }
    __syncthreads();

    const int i = blockIdx.x * 128 + threadIdx.x;
    const float si = score[i];

    int m = i - jlo;                    // local j < m  <=>  global j < i
    m = m < 0 ? 0 : (m > 1024 ? 1024 : m);

    int cnt = 0;
    const float4* sh4 = reinterpret_cast<const float4*>(sh);

    const int m4 = m >> 2;
    for (int q = 0; q < m4; ++q) {
        float4 v = sh4[q];
        cnt += (v.x >= si) + (v.y >= si) + (v.z >= si) + (v.w >= si);
    }
    for (int r = m4 << 2; r < m; ++r) cnt += (sh[r] >= si);

    const int q0 = (m + 3) >> 2;
    int rend = q0 << 2; if (rend > 1024) rend = 1024;
    for (int r = m; r < rend; ++r) cnt += (sh[r] > si);
    for (int q = q0; q < 256; ++q) {
        float4 v = sh4[q];
        cnt += (v.x > si) + (v.y > si) + (v.z > si) + (v.w > si);
    }

    g_partial[blockIdx.y][i] = (unsigned)cnt;
}

// ---------------------------------------------------------------------------
// Stage 2: combine partials; scatter index/score/xyxy/area into sorted rank;
// build the valid bitmask.
// ---------------------------------------------------------------------------
__global__ __launch_bounds__(256) void rank_scatter_kernel(const float* __restrict__ score,
                                                           const float* __restrict__ box)
{
    const int i = blockIdx.x * 256 + threadIdx.x;
    unsigned rank = 0;
#pragma unroll
    for (int k = 0; k < 8; ++k) rank += g_partial[k][i];

    const float s = score[i];
    g_order[rank] = i;
    g_ssort[rank] = s;

    const float4 b = *reinterpret_cast<const float4*>(box + (size_t)i * 16);
    const float hw = __fmul_rn(b.z, 0.5f);
    const float hh = __fmul_rn(b.w, 0.5f);
    const float x1 = __fsub_rn(b.x, hw);
    const float y1 = __fsub_rn(b.y, hh);
    const float x2 = __fadd_rn(b.x, hw);
    const float y2 = __fadd_rn(b.y, hh);
    g_sxyxy[rank] = make_float4(x1, y1, x2, y2);
    g_sarea[rank] = __fmul_rn(__fsub_rn(x2, x1), __fsub_rn(y2, y1));

    if (s >= MIN_SCORE) atomicOr(&g_valid[rank >> 5], 1u << (rank & 31));
}

// ---------------------------------------------------------------------------
// Suppression matrix: g_mask[i] bit j = (IoU(i,j) > thr).
// Block = 256 threads (8 warps); warp owns 32 rows (lane = row), block covers
// 256 rows x 1024 cols.  grid (8 colchunks, 32 rowblocks).  Blocks entirely
// below the diagonal are skipped (those words stay 0 — harmless: ranks < the
// current scan position are never re-examined).  IoU decision uses
// inter > RN(thr * denom)  (no division; same decisions except within ~1 ulp
// of the threshold).
// ---------------------------------------------------------------------------
__global__ __launch_bounds__(256) void mask_kernel()
{
    const int cc = blockIdx.x;             // col chunk of 1024
    const int rb = blockIdx.y;             // row block of 256
    if ((cc + 1) * 1024 <= rb * 256) return;   // whole chunk strictly below diag

    __shared__ float4 sxy[1024];
    __shared__ float  sar[1024];
    const int jbase = cc << 10;
    for (int r = threadIdx.x; r < 1024; r += 256) {
        sxy[r] = g_sxyxy[jbase + r];
        sar[r] = g_sarea[jbase + r];
    }
    __syncthreads();

    const int w = threadIdx.x >> 5, lane = threadIdx.x & 31;
    const int rowbase = (rb << 8) + (w << 5);
    const int i = rowbase + lane;
    const float4 bi = g_sxyxy[i];
    const float  ai = g_sarea[i];

    int jw0 = (rowbase - jbase) >> 5;      // skip words with all j < every lane's i
    if (jw0 < 0) jw0 = 0;

    for (int jw = jw0; jw < 32; ++jw) {
        unsigned word = 0;
#pragma unroll 8
        for (int b = 0; b < 32; ++b) {
            const int jl = (jw << 5) + b;
            const float4 bj = sxy[jl];
            const float  aj = sar[jl];
            const float ltx = fmaxf(bi.x, bj.x);
            const float lty = fmaxf(bi.y, bj.y);
            const float rbx = fminf(bi.z, bj.z);
            const float rby = fminf(bi.w, bj.w);
            const float ww = fmaxf(__fsub_rn(rbx, ltx), 0.0f);
            const float hh = fmaxf(__fsub_rn(rby, lty), 0.0f);
            const float inter = __fmul_rn(ww, hh);
            const float den =
                __fadd_rn(__fsub_rn(__fadd_rn(ai, aj), inter), 1e-9f);
            if (inter > __fmul_rn(NMS_THR, den)) word |= (1u << b);
        }
        g_mask[i][(cc << 5) + jw] = word;
    }
}

// ---------------------------------------------------------------------------
// Sequential scan (warp 0) + output (all 1024 threads).
// suppressed/valid masks live in warp registers: lane t owns words t*8..t*8+7.
// Each kept: ballot-find lowest set bit of (valid & ~suppressed), then OR in
// the kept box's 1KB mask row (coalesced L2 load).
// ---------------------------------------------------------------------------
__global__ __launch_bounds__(1024, 1) void scan_out_kernel(const float* __restrict__ box,
                                                           float* __restrict__ out)
{
    __shared__ int s_kept[MAX_OUT];
    __shared__ int s_nk;

    const int t = threadIdx.x;

    if (t < 32) {
        unsigned sup[8], C[8];
#pragma unroll
        for (int q = 0; q < 8; ++q) {
            sup[q] = 0;
            C[q] = g_valid[t * 8 + q];
        }

        int nk = 0;
        while (nk < MAX_OUT) {
            int localr = 0x7fffffff;
#pragma unroll
            for (int q = 7; q >= 0; --q) {          // descending: smallest q wins
                const unsigned c = C[q] & ~sup[q];
                if (c) localr = ((t * 8 + q) << 5) + (__ffs(c) - 1);
            }
            const unsigned bal = __ballot_sync(0xffffffffu, localr != 0x7fffffff);
            if (!bal) break;
            const int srclane = __ffs(bal) - 1;
            const int r = __shfl_sync(0xffffffffu, localr, srclane);

            if (t == 0) s_kept[nk] = r;
            ++nk;

            // defensively clear the kept bit from C (self-IoU of a degenerate
            // box may not exceed thr, which would otherwise loop forever)
#pragma unroll
            for (int q = 0; q < 8; ++q)
                if (t == (r >> 8) && q == ((r >> 5) & 7)) C[q] &= ~(1u << (r & 31));

            // OR in row r: words t*8 .. t*8+7 (coalesced: lane t reads bytes [32t,32t+32))
            const uint4* rp = reinterpret_cast<const uint4*>(g_mask[r]);
            const uint4 a = rp[t * 2];
            const uint4 b2 = rp[t * 2 + 1];
            sup[0] |= a.x;  sup[1] |= a.y;  sup[2] |= a.z;  sup[3] |= a.w;
            sup[4] |= b2.x; sup[5] |= b2.y; sup[6] |= b2.z; sup[7] |= b2.w;
        }
        if (t == 0) s_nk = nk;
    }
    __syncthreads();

    const int nk = s_nk;

    // Output: [score(256) | box(256x16) | valid(256)] as float32.
    // 4 threads per slot, each writes a float4 of the 16 box coords.
    const int slot = t >> 2, part = t & 3;
    float4 vb = make_float4(0.0f, 0.0f, 0.0f, 0.0f);
    float sc = 0.0f, vl = 0.0f;
    if (slot < nk) {
        const int si = s_kept[slot];
        const int orig = g_order[si];
        vb = *reinterpret_cast<const float4*>(box + (size_t)orig * 16 + part * 4);
        sc = g_ssort[si];
        vl = 1.0f;
    }
    *reinterpret_cast<float4*>(out + 256 + slot * 16 + part * 4) = vb;
    if (part == 0) {
        out[slot] = sc;
        out[4352 + slot] = vl;
    }
}

extern "C" void kernel_launch(void* const* d_in, const int* in_sizes, int n_in,
                              void* d_out, int out_size)
{
    (void)in_sizes; (void)n_in; (void)out_size;
    const float* score = (const float*)d_in[0];
    const float* box   = (const float*)d_in[1];
    float* out = (float*)d_out;

    rank_partial_kernel<<<dim3(64, 8), 128>>>(score);
    rank_scatter_kernel<<<32, 256>>>(score, box);
    mask_kernel<<<dim3(8, 32), 256>>>();
    scan_out_kernel<<<1, 1024>>>(box, out);
}

// round 5
// speedup vs baseline: 2.6438x; 1.0352x over previous
#include <cuda_runtime.h>

#define N 8192
#define NW 256            // 32-bit words per mask row (8192/32)
#define MIN_SCORE 0.3f
#define NMS_THR 0.3f
#define MAX_OUT 256

// scratch (no allocations allowed; zero-initialized at module load)
__device__ int      g_order[N];
__device__ float    g_ssort[N];
__device__ unsigned g_partial[8][N];
__device__ float4   g_sxyxy[N];       // sorted-order xyxy
__device__ float    g_sarea[N];       // sorted-order area
__device__ unsigned g_valid[NW];      // score >= MIN_SCORE, by sorted rank
__device__ unsigned g_mask[N][NW];    // suppression matrix, 8MB (L2-resident)

// ---------------------------------------------------------------------------
// Rank sort, stage 1: partial ranks over a 1024-wide j-tile per block.
// rank(i) = #{j<i : s_j >= s_i} + #{j>=i : s_j > s_i}
// (exactly matches stable argsort(-s): ties broken by ascending index)
// grid (64, 8) x 128 threads.  Block (0,0) also re-zeroes g_valid each launch.
// ---------------------------------------------------------------------------
__global__ __launch_bounds__(128) void rank_partial_kernel(const float* __restrict__ score)
{
    __shared__ float sh[1024];
    const int jlo = blockIdx.y << 10;
    for (int r = threadIdx.x; r < 1024; r += 128) sh[r] = score[jlo + r];
    if (blockIdx.x == 0 && blockIdx.y == 0) {
        g_valid[threadIdx.x] = 0;
        g_valid[threadIdx.x + 128] = 0;
    }
    __syncthreads();

    const int i = blockIdx.x * 128 + threadIdx.x;
    const float si = score[i];

    int m = i - jlo;                    // local j < m  <=>  global j < i
    m = m < 0 ? 0 : (m > 1024 ? 1024 : m);

    int cnt = 0;
    const float4* sh4 = reinterpret_cast<const float4*>(sh);

    const int m4 = m >> 2;
    for (int q = 0; q < m4; ++q) {
        float4 v = sh4[q];
        cnt += (v.x >= si) + (v.y >= si) + (v.z >= si) + (v.w >= si);
    }
    for (int r = m4 << 2; r < m; ++r) cnt += (sh[r] >= si);

    const int q0 = (m + 3) >> 2;
    int rend = q0 << 2; if (rend > 1024) rend = 1024;
    for (int r = m; r < rend; ++r) cnt += (sh[r] > si);
    for (int q = q0; q < 256; ++q) {
        float4 v = sh4[q];
        cnt += (v.x > si) + (v.y > si) + (v.z > si) + (v.w > si);
    }

    g_partial[blockIdx.y][i] = (unsigned)cnt;
}

// ---------------------------------------------------------------------------
// Stage 2: combine partials; scatter index/score/xyxy/area into sorted rank;
// build the valid bitmask.
// ---------------------------------------------------------------------------
__global__ __launch_bounds__(256) void rank_scatter_kernel(const float* __restrict__ score,
                                                           const float* __restrict__ box)
{
    const int i = blockIdx.x * 256 + threadIdx.x;
    unsigned rank = 0;
#pragma unroll
    for (int k = 0; k < 8; ++k) rank += g_partial[k][i];

    const float s = score[i];
    g_order[rank] = i;
    g_ssort[rank] = s;

    const float4 b = *reinterpret_cast<const float4*>(box + (size_t)i * 16);
    const float hw = __fmul_rn(b.z, 0.5f);
    const float hh = __fmul_rn(b.w, 0.5f);
    const float x1 = __fsub_rn(b.x, hw);
    const float y1 = __fsub_rn(b.y, hh);
    const float x2 = __fadd_rn(b.x, hw);
    const float y2 = __fadd_rn(b.y, hh);
    g_sxyxy[rank] = make_float4(x1, y1, x2, y2);
    g_sarea[rank] = __fmul_rn(__fsub_rn(x2, x1), __fsub_rn(y2, y1));

    if (s >= MIN_SCORE) atomicOr(&g_valid[rank >> 5], 1u << (rank & 31));
}

// ---------------------------------------------------------------------------
// Suppression matrix: g_mask[i] bit j = (IoU(i,j) > thr).
// Lower-triangle words may be stale/unwritten — harmless, the scan only ever
// consults bits at ranks above the lowest remaining candidate.
// ---------------------------------------------------------------------------
__global__ __launch_bounds__(256) void mask_kernel()
{
    const int cc = blockIdx.x;             // col chunk of 1024
    const int rb = blockIdx.y;             // row block of 256
    if ((cc + 1) * 1024 <= rb * 256) return;   // whole chunk strictly below diag

    __shared__ float4 sxy[1024];
    __shared__ float  sar[1024];
    const int jbase = cc << 10;
    for (int r = threadIdx.x; r < 1024; r += 256) {
        sxy[r] = g_sxyxy[jbase + r];
        sar[r] = g_sarea[jbase + r];
    }
    __syncthreads();

    const int w = threadIdx.x >> 5, lane = threadIdx.x & 31;
    const int rowbase = (rb << 8) + (w << 5);
    const int i = rowbase + lane;
    const float4 bi = g_sxyxy[i];
    const float  ai = g_sarea[i];

    int jw0 = (rowbase - jbase) >> 5;      // words with all j < every lane's i
    if (jw0 < 0) jw0 = 0;

    for (int jw = jw0; jw < 32; ++jw) {
        unsigned word = 0;
#pragma unroll 8
        for (int b = 0; b < 32; ++b) {
            const int jl = (jw << 5) + b;
            const float4 bj = sxy[jl];
            const float  aj = sar[jl];
            const float ltx = fmaxf(bi.x, bj.x);
            const float lty = fmaxf(bi.y, bj.y);
            const float rbx = fminf(bi.z, bj.z);
            const float rby = fminf(bi.w, bj.w);
            const float ww = fmaxf(__fsub_rn(rbx, ltx), 0.0f);
            const float hh = fmaxf(__fsub_rn(rby, lty), 0.0f);
            const float inter = __fmul_rn(ww, hh);
            const float den =
                __fadd_rn(__fsub_rn(__fadd_rn(ai, aj), inter), 1e-9f);
            if (inter > __fmul_rn(NMS_THR, den)) word |= (1u << b);
        }
        g_mask[i][(cc << 5) + jw] = word;
    }
}

// uniform-index word select over an 8-word row fragment (j is warp-uniform)
__device__ __forceinline__ unsigned word_select(const uint4& a, const uint4& b, int j)
{
    const unsigned r0 = (j & 2) ? ((j & 1) ? a.w : a.z) : ((j & 1) ? a.y : a.x);
    const unsigned r1 = (j & 2) ? ((j & 1) ? b.w : b.z) : ((j & 1) ? b.y : b.x);
    return (j & 4) ? r1 : r0;
}

// ---------------------------------------------------------------------------
// Batched sequential scan (warp 0) + output (256 threads).
// Candidate mask A lives in warp registers: lane t owns words 8t..8t+7.
// Per batch: find 4 lowest candidates, load their 4 mask rows in parallel
// (one memory latency instead of four), resolve exact greedy acceptance via
// uniform word-select + shfl bit tests, OR accepted rows into A once.
// ---------------------------------------------------------------------------
__global__ __launch_bounds__(256, 1) void scan_out_kernel(const float* __restrict__ box,
                                                          float* __restrict__ out)
{
    __shared__ int s_kept[MAX_OUT];
    __shared__ int s_nk;

    const int t = threadIdx.x;
    const unsigned FULL = 0xffffffffu;

    if (t < 32) {
        unsigned A[8];
#pragma unroll
        for (int q = 0; q < 8; ++q) A[q] = g_valid[t * 8 + q];

        int nk = 0;
        while (nk < MAX_OUT) {
            unsigned nzany = 0;
#pragma unroll
            for (int q = 0; q < 8; ++q) nzany |= A[q];
            const unsigned bal = __ballot_sync(FULL, nzany != 0);
            if (!bal) break;
            const int lowlane = __ffs(bal) - 1;

            // every lane extracts its own 4 lowest bit-positions (only
            // lowlane's are consumed); positions are local (0..255)
            unsigned tmp[8];
#pragma unroll
            for (int q = 0; q < 8; ++q) tmp[q] = A[q];
            int loc[4];
#pragma unroll
            for (int k = 0; k < 4; ++k) {
                int pos = -1;
#pragma unroll
                for (int q = 7; q >= 0; --q)
                    if (tmp[q]) pos = (q << 5) + (__ffs(tmp[q]) - 1);
                loc[k] = pos;
#pragma unroll
                for (int q = 0; q < 8; ++q)
                    if (pos >= 0 && (pos >> 5) == q) tmp[q] &= tmp[q] - 1u;
            }

            // broadcast global candidate ranks (uniform afterwards)
            int cand[4];
#pragma unroll
            for (int k = 0; k < 4; ++k) {
                const int lc = __shfl_sync(FULL, loc[k], lowlane);
                cand[k] = (lc < 0) ? -1 : ((lowlane << 8) | lc);
            }

            // parallel row loads: lane t holds words [8t, 8t+8) of each row
            uint4 ra[4], rb[4];
#pragma unroll
            for (int k = 0; k < 4; ++k) {
                if (cand[k] >= 0) {
                    const uint4* rp = reinterpret_cast<const uint4*>(g_mask[cand[k]]);
                    ra[k] = rp[t * 2];
                    rb[k] = rp[t * 2 + 1];
                } else {
                    ra[k] = make_uint4(0, 0, 0, 0);
                    rb[k] = make_uint4(0, 0, 0, 0);
                }
            }

            // exact greedy resolution within the batch
            bool acc[4];
            acc[0] = true; acc[1] = false; acc[2] = false; acc[3] = false;
#pragma unroll
            for (int k = 1; k < 4; ++k) {
                if (cand[k] >= 0) {
                    const int j = (cand[k] >> 5) & 7;
                    const int owner = cand[k] >> 8;
                    const int bit = cand[k] & 31;
                    unsigned w = 0;
#pragma unroll
                    for (int i = 0; i < 4; ++i)
                        if (i < k && acc[i]) w |= word_select(ra[i], rb[i], j);
                    const unsigned sup = (__shfl_sync(FULL, w, owner) >> bit) & 1u;
                    acc[k] = (sup == 0u);
                }
            }

            // apply accepted rows to the candidate mask
            unsigned o0 = 0, o1 = 0, o2 = 0, o3 = 0, o4 = 0, o5 = 0, o6 = 0, o7 = 0;
#pragma unroll
            for (int i = 0; i < 4; ++i) {
                if (cand[i] >= 0 && acc[i]) {
                    o0 |= ra[i].x; o1 |= ra[i].y; o2 |= ra[i].z; o3 |= ra[i].w;
                    o4 |= rb[i].x; o5 |= rb[i].y; o6 |= rb[i].z; o7 |= rb[i].w;
                }
            }
            A[0] &= ~o0; A[1] &= ~o1; A[2] &= ~o2; A[3] &= ~o3;
            A[4] &= ~o4; A[5] &= ~o5; A[6] &= ~o6; A[7] &= ~o7;

            // explicitly clear accepted bits (guards degenerate self-IoU = 0)
#pragma unroll
            for (int i = 0; i < 4; ++i) {
                if (cand[i] >= 0 && acc[i] && t == (cand[i] >> 8)) {
                    const int q = (cand[i] >> 5) & 7;
#pragma unroll
                    for (int qq = 0; qq < 8; ++qq)
                        if (qq == q) A[qq] &= ~(1u << (cand[i] & 31));
                }
            }

            // record kept (uniform bookkeeping)
            int added = 0;
#pragma unroll
            for (int i = 0; i < 4; ++i) {
                if (cand[i] >= 0 && acc[i] && (nk + added) < MAX_OUT) {
                    if (t == 0) s_kept[nk + added] = cand[i];
                    ++added;
                }
            }
            nk += added;
        }
        if (t == 0) s_nk = nk;
    }
    __syncthreads();

    const int nk = s_nk;

    // Output: [score(256) | box(256x16) | valid(256)] as float32.
    // One thread per output slot.
    float4 vb0 = make_float4(0.f, 0.f, 0.f, 0.f), vb1 = vb0, vb2 = vb0, vb3 = vb0;
    float sc = 0.0f, vl = 0.0f;
    if (t < nk) {
        const int si = s_kept[t];
        const int orig = g_order[si];
        const float4* bp = reinterpret_cast<const float4*>(box + (size_t)orig * 16);
        vb0 = bp[0]; vb1 = bp[1]; vb2 = bp[2]; vb3 = bp[3];
        sc = g_ssort[si];
        vl = 1.0f;
    }
    float4* op = reinterpret_cast<float4*>(out + 256 + t * 16);
    op[0] = vb0; op[1] = vb1; op[2] = vb2; op[3] = vb3;
    out[t] = sc;
    out[4352 + t] = vl;
}

extern "C" void kernel_launch(void* const* d_in, const int* in_sizes, int n_in,
                              void* d_out, int out_size)
{
    (void)in_sizes; (void)n_in; (void)out_size;
    const float* score = (const float*)d_in[0];
    const float* box   = (const float*)d_in[1];
    float* out = (float*)d_out;

    rank_partial_kernel<<<dim3(64, 8), 128>>>(score);
    rank_scatter_kernel<<<32, 256>>>(score, box);
    mask_kernel<<<dim3(8, 32), 256>>>();
    scan_out_kernel<<<1, 256>>>(box, out);
}

// round 9
// speedup vs baseline: 3.6749x; 1.3900x over previous
#include <cuda_runtime.h>

#define N 8192
#define NW 256            // 32-bit words per mask row (8192/32)
#define MIN_SCORE 0.3f
#define NMS_THR 0.3f
#define MAX_OUT 256

// scratch (no allocations allowed; zero-initialized at module load)
__device__ int      g_order[N];
__device__ float    g_ssort[N];
__device__ unsigned g_partial[8][N];
__device__ float4   g_sxyxy[N];       // sorted-order xyxy
__device__ float    g_sarea[N];       // sorted-order area
__device__ unsigned g_valid[NW];      // score >= MIN_SCORE, by sorted rank
__device__ unsigned g_mask[N][NW];    // suppression matrix, 8MB (L2-resident)
__device__ unsigned g_diag[NW][32];   // diagonal 32x32 blocks: g_diag[w][i] = g_mask[32w+i][w]

// ---------------------------------------------------------------------------
// Rank sort, stage 1: partial ranks over a 1024-wide j-tile per block.
// rank(i) = #{j<i : s_j >= s_i} + #{j>=i : s_j > s_i}
// (exactly matches stable argsort(-s): ties broken by ascending index)
// grid (64, 8) x 128 threads.  Block (0,0) also re-zeroes g_valid each launch.
// ---------------------------------------------------------------------------
__global__ __launch_bounds__(128) void rank_partial_kernel(const float* __restrict__ score)
{
    __shared__ float sh[1024];
    const int jlo = blockIdx.y << 10;
    for (int r = threadIdx.x; r < 1024; r += 128) sh[r] = score[jlo + r];
    if (blockIdx.x == 0 && blockIdx.y == 0) {
        g_valid[threadIdx.x] = 0;
        g_valid[threadIdx.x + 128] = 0;
    }
    __syncthreads();

    const int i = blockIdx.x * 128 + threadIdx.x;
    const float si = score[i];

    int m = i - jlo;                    // local j < m  <=>  global j < i
    m = m < 0 ? 0 : (m > 1024 ? 1024 : m);

    int cnt = 0;
    const float4* sh4 = reinterpret_cast<const float4*>(sh);

    const int m4 = m >> 2;
    for (int q = 0; q < m4; ++q) {
        float4 v = sh4[q];
        cnt += (v.x >= si) + (v.y >= si) + (v.z >= si) + (v.w >= si);
    }
    for (int r = m4 << 2; r < m; ++r) cnt += (sh[r] >= si);

    const int q0 = (m + 3) >> 2;
    int rend = q0 << 2; if (rend > 1024) rend = 1024;
    for (int r = m; r < rend; ++r) cnt += (sh[r] > si);
    for (int q = q0; q < 256; ++q) {
        float4 v = sh4[q];
        cnt += (v.x > si) + (v.y > si) + (v.z > si) + (v.w > si);
    }

    g_partial[blockIdx.y][i] = (unsigned)cnt;
}

// ---------------------------------------------------------------------------
// Stage 2: combine partials; scatter index/score/xyxy/area into sorted rank;
// build the valid bitmask.
// ---------------------------------------------------------------------------
__global__ __launch_bounds__(256) void rank_scatter_kernel(const float* __restrict__ score,
                                                           const float* __restrict__ box)
{
    const int i = blockIdx.x * 256 + threadIdx.x;
    unsigned rank = 0;
#pragma unroll
    for (int k = 0; k < 8; ++k) rank += g_partial[k][i];

    const float s = score[i];
    g_order[rank] = i;
    g_ssort[rank] = s;

    const float4 b = *reinterpret_cast<const float4*>(box + (size_t)i * 16);
    const float hw = __fmul_rn(b.z, 0.5f);
    const float hh = __fmul_rn(b.w, 0.5f);
    const float x1 = __fsub_rn(b.x, hw);
    const float y1 = __fsub_rn(b.y, hh);
    const float x2 = __fadd_rn(b.x, hw);
    const float y2 = __fadd_rn(b.y, hh);
    g_sxyxy[rank] = make_float4(x1, y1, x2, y2);
    g_sarea[rank] = __fmul_rn(__fsub_rn(x2, x1), __fsub_rn(y2, y1));

    if (s >= MIN_SCORE) atomicOr(&g_valid[rank >> 5], 1u << (rank & 31));
}

// ---------------------------------------------------------------------------
// Suppression matrix: g_mask[i] bit j = (IoU(i,j) > thr).
// Also writes g_diag[w][i&31] = the diagonal 32x32 block word for row i.
// Lower-triangle words may be stale/unwritten — harmless, the scan never
// consults acc bits for already-processed words.
// ---------------------------------------------------------------------------
__global__ __launch_bounds__(256) void mask_kernel()
{
    const int cc = blockIdx.x;             // col chunk of 1024
    const int rb = blockIdx.y;             // row block of 256
    if ((cc + 1) * 1024 <= rb * 256) return;   // whole chunk strictly below diag

    __shared__ float4 sxy[1024];
    __shared__ float  sar[1024];
    const int jbase = cc << 10;
    for (int r = threadIdx.x; r < 1024; r += 256) {
        sxy[r] = g_sxyxy[jbase + r];
        sar[r] = g_sarea[jbase + r];
    }
    __syncthreads();

    const int w = threadIdx.x >> 5, lane = threadIdx.x & 31;
    const int rowbase = (rb << 8) + (w << 5);
    const int i = rowbase + lane;
    const float4 bi = g_sxyxy[i];
    const float  ai = g_sarea[i];

    int jw0 = (rowbase - jbase) >> 5;      // words with all j < every lane's i
    if (jw0 < 0) jw0 = 0;

    const int mydiag = i >> 5;             // global word index of row i's diagonal

    for (int jw = jw0; jw < 32; ++jw) {
        unsigned word = 0;
#pragma unroll 8
        for (int b = 0; b < 32; ++b) {
            const int jl = (jw << 5) + b;
            const float4 bj = sxy[jl];
            const float  aj = sar[jl];
            const float ltx = fmaxf(bi.x, bj.x);
            const float lty = fmaxf(bi.y, bj.y);
            const float rbx = fminf(bi.z, bj.z);
            const float rby = fminf(bi.w, bj.w);
            const float ww = fmaxf(__fsub_rn(rbx, ltx), 0.0f);
            const float hh = fmaxf(__fsub_rn(rby, lty), 0.0f);
            const float inter = __fmul_rn(ww, hh);
            const float den =
                __fadd_rn(__fsub_rn(__fadd_rn(ai, aj), inter), 1e-9f);
            if (inter > __fmul_rn(NMS_THR, den)) word |= (1u << b);
        }
        const int gw = (cc << 5) + jw;
        g_mask[i][gw] = word;
        if (gw == mydiag) g_diag[mydiag][lane] = word;
    }
}

// ---------------------------------------------------------------------------
// Word-parallel greedy scan + output (256 threads, 1 block).
// Thread t owns suppression-acc word t (register). Per 32-rank word step:
//   1. owner thread publishes alive = valid & ~acc
//   2. warp 0 resolves intra-word greedy from the smem-staged diagonal block
//      (fast path: one REDUX.OR proves no intra-word suppression -> keep all)
//   3. all 256 threads OR the kept rows' word t from g_mask (coalesced, MLP~22)
// Stops as soon as MAX_OUT kept are found (~13 word steps on this data).
// ---------------------------------------------------------------------------
__global__ __launch_bounds__(256, 1) void scan_out_kernel(const float* __restrict__ box,
                                                          float* __restrict__ out)
{
    __shared__ unsigned s_diag[NW][32];   // 32KB
    __shared__ unsigned s_alive, s_kw;
    __shared__ int s_nk, s_stop;
    __shared__ int s_kept[MAX_OUT];

    const int t = threadIdx.x;
    const unsigned FULL = 0xffffffffu;

    // stage all diagonal blocks into smem (coalesced 32KB burst)
    {
        const uint4* src = reinterpret_cast<const uint4*>(&g_diag[0][0]);
        uint4* dst = reinterpret_cast<uint4*>(&s_diag[0][0]);
        for (int q = t; q < NW * 8; q += 256) dst[q] = src[q];
    }
    unsigned acc = 0;
    const unsigned validw = g_valid[t];
    if (t == 0) { s_nk = 0; s_stop = 0; }
    __syncthreads();

    int nk = 0;   // maintained uniformly by warp 0
    for (int w = 0; w < NW; ++w) {
        if (t == w) s_alive = validw & ~acc;
        __syncthreads();

        if (t < 32) {
            const unsigned alive = s_alive;
            unsigned kept = 0;
            if (alive) {
                const unsigned B = s_diag[w][t];
                // does any alive candidate get suppressed by an alive earlier one?
                const unsigned C = ((alive >> t) & 1u) ? (B & (0xFFFFFFFEu << t)) : 0u;
                const unsigned S = __reduce_or_sync(FULL, C);
                if ((alive & S) == 0u) {
                    kept = alive;                    // fast path: keep all alive
                } else {
                    unsigned cur = alive;            // exact serial greedy
                    while (cur) {
                        const int i = __ffs(cur) - 1;
                        kept |= 1u << i;
                        const unsigned row = __shfl_sync(FULL, B, i);
                        cur &= ~(1u << i);
                        cur &= ~row;
                    }
                }
            }
            const int cnt = __popc(kept);
            if ((kept >> t) & 1u) {
                const int pos = __popc(kept & ((1u << t) - 1u));
                if (nk + pos < MAX_OUT) s_kept[nk + pos] = (w << 5) + t;
            }
            nk += cnt;
            if (nk >= MAX_OUT) { nk = MAX_OUT; if (t == 0) s_stop = 1; }
            if (t == 0) { s_kw = kept; s_nk = nk; }
        }
        __syncthreads();

        if (s_stop) break;                    // uniform
        unsigned kw = s_kw;
        if (kw) {
            unsigned orv = 0;
            while (kw) {                      // ~22 independent coalesced LDGs
                const int j = __ffs(kw) - 1;
                kw &= kw - 1u;
                orv |= g_mask[(w << 5) + j][t];
            }
            acc |= orv;
        }
    }
    __syncthreads();

    const int nkf = s_nk;

    // Output: [score(256) | box(256x16) | valid(256)] as float32.
    float4 vb0 = make_float4(0.f, 0.f, 0.f, 0.f), vb1 = vb0, vb2 = vb0, vb3 = vb0;
    float sc = 0.0f, vl = 0.0f;
    if (t < nkf) {
        const int si = s_kept[t];
        const int orig = g_order[si];
        const float4* bp = reinterpret_cast<const float4*>(box + (size_t)orig * 16);
        vb0 = bp[0]; vb1 = bp[1]; vb2 = bp[2]; vb3 = bp[3];
        sc = g_ssort[si];
        vl = 1.0f;
    }
    float4* op = reinterpret_cast<float4*>(out + 256 + t * 16);
    op[0] = vb0; op[1] = vb1; op[2] = vb2; op[3] = vb3;
    out[t] = sc;
    out[4352 + t] = vl;
}

extern "C" void kernel_launch(void* const* d_in, const int* in_sizes, int n_in,
                              void* d_out, int out_size)
{
    (void)in_sizes; (void)n_in; (void)out_size;
    const float* score = (const float*)d_in[0];
    const float* box   = (const float*)d_in[1];
    float* out = (float*)d_out;

    rank_partial_kernel<<<dim3(64, 8), 128>>>(score);
    rank_scatter_kernel<<<32, 256>>>(score, box);
    mask_kernel<<<dim3(8, 32), 256>>>();
    scan_out_kernel<<<1, 256>>>(box, out);
}

// round 12
// speedup vs baseline: 5.1010x; 1.3881x over previous
#include <cuda_runtime.h>

#define N 8192
#define NW 256            // 32-bit words per mask row (8192/32)
#define MIN_SCORE 0.3f
#define NMS_THR 0.3f
#define MAX_OUT 256

// scratch (no allocations allowed; zero-initialized at module load)
__device__ int      g_order[N];
__device__ float    g_ssort[N];
__device__ unsigned g_partial[8][N];
__device__ float4   g_sxyxy[N];       // sorted-order xyxy
__device__ float    g_sarea[N];       // sorted-order area
__device__ unsigned g_valid[NW];      // score >= MIN_SCORE, by sorted rank
__device__ unsigned g_mask[N][NW];    // suppression matrix, 8MB (L2-resident)

// ---------------------------------------------------------------------------
// Rank sort, stage 1: partial ranks over a 1024-wide j-tile per block.
// rank(i) = #{j<i : s_j >= s_i} + #{j>=i : s_j > s_i}
// (exactly matches stable argsort(-s): ties broken by ascending index)
// grid (64, 8) x 128 threads.  Block (0,0) also re-zeroes g_valid each launch.
// ---------------------------------------------------------------------------
__global__ __launch_bounds__(128) void rank_partial_kernel(const float* __restrict__ score)
{
    __shared__ float sh[1024];
    const int jlo = blockIdx.y << 10;
    for (int r = threadIdx.x; r < 1024; r += 128) sh[r] = score[jlo + r];
    if (blockIdx.x == 0 && blockIdx.y == 0) {
        g_valid[threadIdx.x] = 0;
        g_valid[threadIdx.x + 128] = 0;
    }
    __syncthreads();

    const int i = blockIdx.x * 128 + threadIdx.x;
    const float si = score[i];

    int m = i - jlo;                    // local j < m  <=>  global j < i
    m = m < 0 ? 0 : (m > 1024 ? 1024 : m);

    int cnt = 0;
    const float4* sh4 = reinterpret_cast<const float4*>(sh);

    const int m4 = m >> 2;
    for (int q = 0; q < m4; ++q) {
        float4 v = sh4[q];
        cnt += (v.x >= si) + (v.y >= si) + (v.z >= si) + (v.w >= si);
    }
    for (int r = m4 << 2; r < m; ++r) cnt += (sh[r] >= si);

    const int q0 = (m + 3) >> 2;
    int rend = q0 << 2; if (rend > 1024) rend = 1024;
    for (int r = m; r < rend; ++r) cnt += (sh[r] > si);
    for (int q = q0; q < 256; ++q) {
        float4 v = sh4[q];
        cnt += (v.x > si) + (v.y > si) + (v.z > si) + (v.w > si);
    }

    g_partial[blockIdx.y][i] = (unsigned)cnt;
}

// ---------------------------------------------------------------------------
// Stage 2: combine partials; scatter index/score/xyxy/area into sorted rank;
// build the valid bitmask.
// ---------------------------------------------------------------------------
__global__ __launch_bounds__(256) void rank_scatter_kernel(const float* __restrict__ score,
                                                           const float* __restrict__ box)
{
    const int i = blockIdx.x * 256 + threadIdx.x;
    unsigned rank = 0;
#pragma unroll
    for (int k = 0; k < 8; ++k) rank += g_partial[k][i];

    const float s = score[i];
    g_order[rank] = i;
    g_ssort[rank] = s;

    const float4 b = *reinterpret_cast<const float4*>(box + (size_t)i * 16);
    const float hw = __fmul_rn(b.z, 0.5f);
    const float hh = __fmul_rn(b.w, 0.5f);
    const float x1 = __fsub_rn(b.x, hw);
    const float y1 = __fsub_rn(b.y, hh);
    const float x2 = __fadd_rn(b.x, hw);
    const float y2 = __fadd_rn(b.y, hh);
    g_sxyxy[rank] = make_float4(x1, y1, x2, y2);
    g_sarea[rank] = __fmul_rn(__fsub_rn(x2, x1), __fsub_rn(y2, y1));

    if (s >= MIN_SCORE) atomicOr(&g_valid[rank >> 5], 1u << (rank & 31));
}

// ---------------------------------------------------------------------------
// Suppression matrix: g_mask[i] bit j = (IoU(i,j) > thr).
// Lower-triangle words may be stale/unwritten — harmless, the scan only ANDs
// them into alive-words that are already zero.
// ---------------------------------------------------------------------------
__global__ __launch_bounds__(256) void mask_kernel()
{
    const int cc = blockIdx.x;             // col chunk of 1024
    const int rb = blockIdx.y;             // row block of 256
    if ((cc + 1) * 1024 <= rb * 256) return;   // whole chunk strictly below diag

    __shared__ float4 sxy[1024];
    __shared__ float  sar[1024];
    const int jbase = cc << 10;
    for (int r = threadIdx.x; r < 1024; r += 256) {
        sxy[r] = g_sxyxy[jbase + r];
        sar[r] = g_sarea[jbase + r];
    }
    __syncthreads();

    const int w = threadIdx.x >> 5, lane = threadIdx.x & 31;
    const int rowbase = (rb << 8) + (w << 5);
    const int i = rowbase + lane;
    const float4 bi = g_sxyxy[i];
    const float  ai = g_sarea[i];

    int jw0 = (rowbase - jbase) >> 5;      // words with all j < every lane's i
    if (jw0 < 0) jw0 = 0;

    for (int jw = jw0; jw < 32; ++jw) {
        unsigned word = 0;
#pragma unroll 8
        for (int b = 0; b < 32; ++b) {
            const int jl = (jw << 5) + b;
            const float4 bj = sxy[jl];
            const float  aj = sar[jl];
            const float ltx = fmaxf(bi.x, bj.x);
            const float lty = fmaxf(bi.y, bj.y);
            const float rbx = fminf(bi.z, bj.z);
            const float rby = fminf(bi.w, bj.w);
            const float ww = fmaxf(__fsub_rn(rbx, ltx), 0.0f);
            const float hh = fmaxf(__fsub_rn(rby, lty), 0.0f);
            const float inter = __fmul_rn(ww, hh);
            const float den =
                __fadd_rn(__fsub_rn(__fadd_rn(ai, aj), inter), 1e-9f);
            if (inter > __fmul_rn(NMS_THR, den)) word |= (1u << b);
        }
        g_mask[i][(cc << 5) + jw] = word;
    }
}

// ---------------------------------------------------------------------------
// Hierarchical greedy scan + output (256 threads, 1 block, 128KB dyn smem).
// 8 super-blocks of 1024 ranks. Per super-block:
//   stage:   1024x32-word diagonal bit-block from L2 into smem (coalesced)
//   resolve: ONE warp, kept-driven — per kept box: ballot-find lowest alive
//            bit + one conflict-free LDS row + AND (~100cyc, smem only)
//   apply:   all 256 threads OR the new kept rows' word t (register acc,
//            coalesced L2, one latency for ~30 rows)
// ---------------------------------------------------------------------------
__global__ __launch_bounds__(256, 1) void scan_out_kernel(const float* __restrict__ box,
                                                          float* __restrict__ out)
{
    extern __shared__ unsigned sb[];      // [1024][32] words = 128KB
    __shared__ unsigned s_alive[32];
    __shared__ int s_kept[MAX_OUT];
    __shared__ int s_nk, s_nk_prev, s_stop;

    const int t = threadIdx.x;
    const unsigned FULL = 0xffffffffu;

    unsigned acc = 0;                     // thread t owns suppression word t
    const unsigned validw = g_valid[t];
    if (t == 0) { s_nk = 0; s_stop = 0; }

    for (int b = 0; b < 8; ++b) {
        // ---- stage diag block: rows [1024b, 1024b+1024), words [32b, 32b+32)
        {
            const int rbase = b << 10;
            uint4* dst = reinterpret_cast<uint4*>(sb);
            for (int q = t; q < 8192; q += 256) {
                const int row = q >> 3, seg = q & 7;
                dst[(row << 3) + seg] =
                    reinterpret_cast<const uint4*>(g_mask[rbase + row])[(b << 3) + seg];
            }
        }
        // ---- publish this block's alive words
        if ((t >> 5) == b) s_alive[t & 31] = validw & ~acc;
        __syncthreads();

        // ---- resolve (warp 0, kept-driven)
        if (t < 32) {
            unsigned alive = s_alive[t];
            int nk = s_nk;
            if (t == 0) s_nk_prev = nk;
            while (nk < MAX_OUT) {
                const unsigned bal = __ballot_sync(FULL, alive != 0);
                if (!bal) break;
                const int low = __ffs(bal) - 1;                 // lowest nonempty word
                const unsigned aw = __shfl_sync(FULL, alive, low);
                const int bit = __ffs(aw) - 1;
                const int rl = (low << 5) + bit;                // kept (lowest alive)
                if (t == 0) s_kept[nk] = (b << 10) + rl;
                ++nk;
                const unsigned row = sb[(rl << 5) + t];         // conflict-free LDS
                if (t == low) alive &= ~(1u << bit);            // clear self
                alive &= ~row;
            }
            if (t == 0) { s_nk = nk; s_stop = (nk >= MAX_OUT); }
        }
        __syncthreads();

        if (s_stop) break;                                      // uniform

        // ---- apply new kept rows to future words (register acc)
        const int k0 = s_nk_prev, k1 = s_nk;
        for (int k = k0; k < k1; ++k)
            acc |= g_mask[s_kept[k]][t];
        // (next iteration's first barrier orders apply vs. re-publish)
    }
    __syncthreads();

    const int nkf = s_nk;

    // Output: [score(256) | box(256x16) | valid(256)] as float32.
    float4 vb0 = make_float4(0.f, 0.f, 0.f, 0.f), vb1 = vb0, vb2 = vb0, vb3 = vb0;
    float sc = 0.0f, vl = 0.0f;
    if (t < nkf) {
        const int si = s_kept[t];
        const int orig = g_order[si];
        const float4* bp = reinterpret_cast<const float4*>(box + (size_t)orig * 16);
        vb0 = bp[0]; vb1 = bp[1]; vb2 = bp[2]; vb3 = bp[3];
        sc = g_ssort[si];
        vl = 1.0f;
    }
    float4* op = reinterpret_cast<float4*>(out + 256 + t * 16);
    op[0] = vb0; op[1] = vb1; op[2] = vb2; op[3] = vb3;
    out[t] = sc;
    out[4352 + t] = vl;
}

extern "C" void kernel_launch(void* const* d_in, const int* in_sizes, int n_in,
                              void* d_out, int out_size)
{
    (void)in_sizes; (void)n_in; (void)out_size;
    const float* score = (const float*)d_in[0];
    const float* box   = (const float*)d_in[1];
    float* out = (float*)d_out;

    const int scan_smem = 1024 * 32 * (int)sizeof(unsigned);   // 128KB
    cudaFuncSetAttribute(scan_out_kernel,
                         cudaFuncAttributeMaxDynamicSharedMemorySize, scan_smem);

    rank_partial_kernel<<<dim3(64, 8), 128>>>(score);
    rank_scatter_kernel<<<32, 256>>>(score, box);
    mask_kernel<<<dim3(8, 32), 256>>>();
    scan_out_kernel<<<1, 256, scan_smem>>>(box, out);
}